// round 13
// baseline (speedup 1.0000x reference)
#include <cuda_runtime.h>
#include <math.h>

#define FRAME_SIZE 160
#define LPC_N 16
#define T_LEN 2400
#define T4 (T_LEN / 4)                 // 600 float4 groups per row
#define N_FRAMES 15
#define B_SZ 1024

#define OG 60                          // output groups per chunk (240 samples)
#define CHUNKS_PER_ROW (T4 / OG)       // 10
#define NTHREADS 64                    // 60 work + 4 halo threads
#define NBLOCKS (B_SZ * CHUNKS_PER_ROW)  // 10240

#define SCALE    (255.0f / 32768.0f)
#define SCALE_1  (32768.0f / 255.0f)

__device__ __forceinline__ float ex2_approx(float x) {
    float y; asm("ex2.approx.f32 %0, %1;" : "=f"(y) : "f"(x)); return y;
}
__device__ __forceinline__ float lg2_approx(float x) {
    float y; asm("lg2.approx.f32 %0, %1;" : "=f"(y) : "f"(x)); return y;
}

// mu-law decode, folded: w = v/16 - 8  =>  linear = copysign(SCALE_1*(2^|w|-1), w)
// (4 instructions: FFMA, MUFU.EX2 (|.| folded into FMUL-free operand), FFMA, LOP3)
__device__ __forceinline__ float u2l(float v) {
    float w = fmaf(v, 0.0625f, -8.0f);
    float m = fmaf(SCALE_1, ex2_approx(fabsf(w)), -SCALE_1);
    return copysignf(m, w);
}
// l2u(-a) = clip(128 - copysign(16*log2(1 + SCALE*|a|), a), 0, 255)
__device__ __forceinline__ float l2u_neg(float a) {
    float u = lg2_approx(fmaf(SCALE, fabsf(a), 1.0f));
    float s = copysignf(16.0f, a);
    return fminf(fmaxf(fmaf(-s, u, 128.0f), 0.0f), 255.0f);
}

__device__ __forceinline__ float4 dec4(float4 v) {
    float4 d;
    d.x = u2l(v.x); d.y = u2l(v.y); d.z = u2l(v.z); d.w = u2l(v.w);
    return d;
}

// R8 structure, polished:
//  - 64-thread blocks (2 warps/barrier), one block per (row, 60-group chunk)
//  - work thread keeps its OWN decoded group in registers (x[16..19]) and
//    reads only 4 lower groups from shared (4 LDS.128 instead of 5)
//  - coeff LDG prefetch front-batched with the sig load (as R8)
__global__ __launch_bounds__(NTHREADS)
void diff_pred_kernel(const float4* __restrict__ sig,
                      const float*  __restrict__ lpc,
                      float4* __restrict__ out) {
    __shared__ __align__(16) float4 sx4[4 + OG];   // halo + decoded chunk

    const int bx  = blockIdx.x;
    const int b   = bx / CHUNKS_PER_ROW;
    const int ck  = bx % CHUNKS_PER_ROW;
    const int gb  = ck * OG;                 // row-local group base
    const int tid = threadIdx.x;

    const float4* srow = sig + (size_t)b * T4;

    // ---- front-batch all global loads, decode, stage ----
    float4 c0, c1, c2, c3, d;
    if (tid < OG) {
        float4 v = srow[gb + tid];
        const int f = (gb + tid) / (FRAME_SIZE / 4);   // frame = G/40
        const float4* lrow = (const float4*)(lpc + (size_t)b * (N_FRAMES * LPC_N)
                                             + f * LPC_N);
        c0 = lrow[0]; c1 = lrow[1]; c2 = lrow[2]; c3 = lrow[3];
        d = dec4(v);
        sx4[4 + tid] = d;
    } else {
        // halo: groups gb-4 .. gb-1 (value 128 decodes to exact linear zero)
        const int k = tid - OG;              // 0..3
        float4 h = (ck == 0) ? make_float4(128.f, 128.f, 128.f, 128.f)
                             : srow[gb - 4 + k];
        sx4[k] = dec4(h);
    }
    __syncthreads();

    if (tid >= OG) return;

    // window x[0..15] from shared (4 LDS.128); x[16..19] = own decode (regs)
    float x[20];
#pragma unroll
    for (int k = 0; k < 4; ++k) {
        float4 xx = sx4[tid + k];
        x[4 * k] = xx.x; x[4 * k + 1] = xx.y; x[4 * k + 2] = xx.z; x[4 * k + 3] = xx.w;
    }
    x[16] = d.x; x[17] = d.y; x[18] = d.z; x[19] = d.w;

    const float c[LPC_N] = { c0.x, c0.y, c0.z, c0.w, c1.x, c1.y, c1.z, c1.w,
                             c2.x, c2.y, c2.z, c2.w, c3.x, c3.y, c3.z, c3.w };

    // output sample 4*(gb+tid) + j uses x[16 + j - i]
    float a0 = 0.f, a1 = 0.f, a2 = 0.f, a3 = 0.f;
#pragma unroll
    for (int i = 0; i < LPC_N; ++i) {
        a0 = fmaf(c[i], x[16 - i], a0);
        a1 = fmaf(c[i], x[17 - i], a1);
        a2 = fmaf(c[i], x[18 - i], a2);
        a3 = fmaf(c[i], x[19 - i], a3);
    }

    float4 r;
    r.x = l2u_neg(a0); r.y = l2u_neg(a1); r.z = l2u_neg(a2); r.w = l2u_neg(a3);
    out[(size_t)b * T4 + gb + tid] = r;
}

extern "C" void kernel_launch(void* const* d_in, const int* in_sizes, int n_in,
                              void* d_out, int out_size) {
    const float4* sig = (const float4*)d_in[0];  // (B, 2400, 1) f32
    const float*  lpc = (const float*)d_in[1];   // (B, 15, 16) f32
    float4* out = (float4*)d_out;                // (B, 2400, 1) f32

    diff_pred_kernel<<<NBLOCKS, NTHREADS>>>(sig, lpc, out);
}

// round 14
// speedup vs baseline: 1.0299x; 1.0299x over previous
#include <cuda_runtime.h>
#include <math.h>

#define FRAME_SIZE 160
#define LPC_N 16
#define T_LEN 2400
#define T4 (T_LEN / 4)                 // 600 float4 per row
#define N_FRAMES 15
#define B_SZ 1024

#define FPB 3                          // frames per block
#define CHUNK (FRAME_SIZE * FPB)       // 480 samples
#define CHUNK4 (CHUNK / 4)             // 120 float4
#define CHUNKS_PER_B (N_FRAMES / FPB)  // 5
#define NTHREADS 128
#define NWORK CHUNK4                   // 120 work threads, 4 samples each

#define SCALE    (255.0f / 32768.0f)
#define SCALE_1  (32768.0f / 255.0f)

__device__ __forceinline__ float ex2_approx(float x) {
    float y; asm("ex2.approx.f32 %0, %1;" : "=f"(y) : "f"(x)); return y;
}
__device__ __forceinline__ float lg2_approx(float x) {
    float y; asm("lg2.approx.f32 %0, %1;" : "=f"(y) : "f"(x)); return y;
}

// mu-law decode, folded: w = v/16 - 8  =>  linear = copysign(SCALE_1*(2^|w|-1), w)
// u2l(128) == +0 exactly (history pad).
__device__ __forceinline__ float u2l(float v) {
    float w = fmaf(v, 0.0625f, -8.0f);
    float m = fmaf(SCALE_1, ex2_approx(fabsf(w)), -SCALE_1);
    return copysignf(m, w);
}
// l2u(-a) = clip(128 - copysign(16*log2(1 + SCALE*|a|), a), 0, 255)
__device__ __forceinline__ float l2u_neg(float a) {
    float u = lg2_approx(fmaf(SCALE, fabsf(a), 1.0f));
    float s = copysignf(16.0f, a);
    return fminf(fmaxf(fmaf(-s, u, 128.0f), 0.0f), 255.0f);
}

__device__ __forceinline__ float4 dec4(float4 v) {
    float4 d;
    d.x = u2l(v.x); d.y = u2l(v.y); d.z = u2l(v.z); d.w = u2l(v.w);
    return d;
}

// R8 champion, verbatim structure + two register-neutral micro-cuts:
//  (a) folded decode (one fewer instr/sample)
//  (b) own-group register bypass: x[16..19] from this thread's own decode,
//      only 4 LDS.128 for the lower window.
__global__ __launch_bounds__(NTHREADS)
void diff_pred_kernel(const float4* __restrict__ sig,
                      const float*  __restrict__ lpc,
                      float4* __restrict__ out) {
    __shared__ __align__(16) float sx[LPC_N + CHUNK];   // halo + decoded chunk
    float4* sx4 = (float4*)sx;

    const int bx  = blockIdx.x;
    const int b   = bx / CHUNKS_PER_B;
    const int ck  = bx % CHUNKS_PER_B;
    const int tid = threadIdx.x;
    const int row4 = b * T4 + ck * CHUNK4;   // float4 index of chunk start

    // ---- front-batch ALL global loads (sig + this thread's coefficients) ----
    float4 c0, c1, c2, c3, d;
    if (tid < NWORK) {
        float4 v = sig[row4 + tid];
        // frame of this thread's 4 samples: tid/40 (0..2)
        const int f = tid / (FRAME_SIZE / 4);
        const float4* lrow = (const float4*)(lpc + (size_t)b * (N_FRAMES * LPC_N)
                                             + (ck * FPB + f) * LPC_N);
        c0 = lrow[0]; c1 = lrow[1]; c2 = lrow[2]; c3 = lrow[3];
        d = dec4(v);
        sx4[4 + tid] = d;
    } else if (tid < NWORK + 4) {
        // halo: 16 samples preceding the chunk (128 decodes to exact linear 0)
        int k = tid - NWORK;                 // 0..3
        float4 h = (ck == 0) ? make_float4(128.f, 128.f, 128.f, 128.f)
                             : sig[row4 - 4 + k];
        sx4[k] = dec4(h);
    }
    __syncthreads();

    if (tid >= NWORK) return;

    // window x[0..15] from shared (4 LDS.128); x[16..19] = own decode (regs)
    float x[20];
#pragma unroll
    for (int k = 0; k < 4; ++k) {
        float4 xx = sx4[tid + k];
        x[4 * k] = xx.x; x[4 * k + 1] = xx.y; x[4 * k + 2] = xx.z; x[4 * k + 3] = xx.w;
    }
    x[16] = d.x; x[17] = d.y; x[18] = d.z; x[19] = d.w;

    const float c[LPC_N] = { c0.x, c0.y, c0.z, c0.w, c1.x, c1.y, c1.z, c1.w,
                             c2.x, c2.y, c2.z, c2.w, c3.x, c3.y, c3.z, c3.w };

    // output sample 4*tid + j uses x[16 + j - i], i = 0..15
    float a0 = 0.f, a1 = 0.f, a2 = 0.f, a3 = 0.f;
#pragma unroll
    for (int i = 0; i < LPC_N; ++i) {
        a0 = fmaf(c[i], x[16 - i], a0);
        a1 = fmaf(c[i], x[17 - i], a1);
        a2 = fmaf(c[i], x[18 - i], a2);
        a3 = fmaf(c[i], x[19 - i], a3);
    }

    float4 r;
    r.x = l2u_neg(a0); r.y = l2u_neg(a1); r.z = l2u_neg(a2); r.w = l2u_neg(a3);
    out[row4 + tid] = r;
}

extern "C" void kernel_launch(void* const* d_in, const int* in_sizes, int n_in,
                              void* d_out, int out_size) {
    const float4* sig = (const float4*)d_in[0];  // (B, 2400, 1) f32
    const float*  lpc = (const float*)d_in[1];   // (B, 15, 16) f32
    float4* out = (float4*)d_out;                // (B, 2400, 1) f32

    dim3 grid(B_SZ * CHUNKS_PER_B);              // 5120 blocks
    dim3 block(NTHREADS);
    diff_pred_kernel<<<grid, block>>>(sig, lpc, out);
}